// round 1
// baseline (speedup 1.0000x reference)
#include <cuda_runtime.h>
#include <cuda_bf16.h>
#include <cstdint>

// ---------------------------------------------------------------------------
// S6 block: proj GEMM (bf16 3-term split) -> elementwise -> chunked scan ->
// output GEMM (bf16 3-term split).
// Shapes fixed per problem: B=4, L=4096, Cin=256, N=512, Cout=256.
// ---------------------------------------------------------------------------

constexpr int kBL   = 16384;   // B*L rows
constexpr int kCin  = 256;
constexpr int kN    = 512;     // state dim
constexpr int kCout = 256;
constexpr int kKP1  = 768;     // packed K for gemm1 (3 * 256)
constexpr int kNP1  = 2048;    // gemm1 cols: [x_proj | Bm | C | delta]
constexpr int kKP2  = 1536;    // packed K for gemm2 (3 * 512)
constexpr int kL    = 4096;
constexpr int kB    = 4;
constexpr int kNCH  = 32;      // scan chunks per sequence
constexpr int kCH   = 128;     // chunk length

// ------------------------- scratch (device globals) ------------------------
__device__ __nv_bfloat16 g_xp  [(size_t)kBL * kKP1];
__device__ __nv_bfloat16 g_Wp1 [(size_t)kKP1 * kNP1];
__device__ float         g_proj[(size_t)kBL * kNP1];
__device__ float         g_a   [(size_t)kBL * kN];
__device__ float         g_u   [(size_t)kBL * kN];
__device__ float         g_c   [(size_t)kBL * kN];
__device__ float         g_Ag  [kB * kNCH * kN];
__device__ float         g_Bg  [kB * kNCH * kN];
__device__ float         g_H   [kB * kNCH * kN];
__device__ __nv_bfloat16 g_y1p [(size_t)kBL * kKP2];
__device__ __nv_bfloat16 g_Wyp [(size_t)kKP2 * kCout];

// ------------------------------- helpers -----------------------------------
__device__ __forceinline__ uint32_t smem_u32(const void* p) {
    return (uint32_t)__cvta_generic_to_shared(p);
}

// ------------------------------ pack kernels --------------------------------
// xpack = [hi | hi | lo] along K
__global__ void pack_x_kernel(const float* __restrict__ x) {
    int idx = blockIdx.x * 256 + threadIdx.x;        // < kBL*kKP1
    int row = idx / kKP1;
    int kk  = idx - row * kKP1;
    int seg = kk >> 8;                               // 0,1,2
    int k   = kk & 255;
    float v = x[(size_t)row * kCin + k];
    __nv_bfloat16 hi = __float2bfloat16(v);
    __nv_bfloat16 o  = hi;
    if (seg == 2) o = __float2bfloat16(v - __bfloat162float(hi));
    g_xp[(size_t)row * kKP1 + kk] = o;
}

// Wpack = [hi | lo | hi] along K; columns = [Wx(512) | Bm(512) | C(512) | Wd(512)]
__global__ void pack_w1_kernel(const float* __restrict__ Wx,
                               const float* __restrict__ Wbc,
                               const float* __restrict__ Wd) {
    int idx = blockIdx.x * 256 + threadIdx.x;        // < kKP1*kNP1
    int kk  = idx / kNP1;
    int j   = idx - kk * kNP1;
    int seg = kk >> 8;
    int k   = kk & 255;
    float w;
    if (j < 512)        w = Wx [k * 512  + j];
    else if (j < 1536)  w = Wbc[k * 1024 + (j - 512)];   // Bm cols 0-511, C cols 512-1023
    else                w = Wd [k * 512  + (j - 1536)];
    __nv_bfloat16 hi = __float2bfloat16(w);
    __nv_bfloat16 o  = hi;
    if (seg == 1) o = __float2bfloat16(w - __bfloat162float(hi));
    g_Wp1[(size_t)kk * kNP1 + j] = o;
}

__global__ void pack_wy_kernel(const float* __restrict__ Wy) {
    int idx = blockIdx.x * 256 + threadIdx.x;        // < kKP2*kCout
    int kk  = idx / kCout;
    int j   = idx - kk * kCout;
    int seg = kk / kN;                               // 0,1,2
    int k   = kk - seg * kN;
    float w = Wy[k * kCout + j];
    __nv_bfloat16 hi = __float2bfloat16(w);
    __nv_bfloat16 o  = hi;
    if (seg == 1) o = __float2bfloat16(w - __bfloat162float(hi));
    g_Wyp[(size_t)kk * kCout + j] = o;
}

// ------------------------------ GEMM (bf16 mma) -----------------------------
#define GBM 128
#define GBN 128
#define GBK 32
#define APAD 8
#define BPAD 8

template <bool HAS_BIAS>
__global__ void __launch_bounds__(256)
gemm_bf16_split(const __nv_bfloat16* __restrict__ A,
                const __nv_bfloat16* __restrict__ B,
                const float* __restrict__ bias,
                float* __restrict__ C,
                int M, int N, int K) {
    __shared__ __align__(16) __nv_bfloat16 As[2][GBM][GBK + APAD];
    __shared__ __align__(16) __nv_bfloat16 Bs[2][GBK][GBN + BPAD];

    const int tid  = threadIdx.x;
    const int lane = tid & 31;
    const int warp = tid >> 5;
    const int wm   = (warp >> 2) * 64;   // warp tile 64x32, warp grid 2x4
    const int wn   = (warp & 3) * 32;
    const int bm   = blockIdx.y * GBM;
    const int bn   = blockIdx.x * GBN;

    float acc[4][4][4];
#pragma unroll
    for (int i = 0; i < 4; i++)
#pragma unroll
        for (int j = 0; j < 4; j++)
#pragma unroll
            for (int q = 0; q < 4; q++) acc[i][j][q] = 0.f;

    const int KT = K / GBK;

    auto load_tiles = [&](int kt, int s) {
#pragma unroll
        for (int i = 0; i < 2; i++) {                 // A: 128 rows x 32 = 512 x 16B
            int v = tid + i * 256;
            int row = v >> 2, seg = v & 3;
            const __nv_bfloat16* gp = A + (size_t)(bm + row) * K + kt * GBK + seg * 8;
            asm volatile("cp.async.cg.shared.global [%0], [%1], 16;\n" ::
                         "r"(smem_u32(&As[s][row][seg * 8])), "l"(gp));
        }
#pragma unroll
        for (int i = 0; i < 2; i++) {                 // B: 32 rows x 128 = 512 x 16B
            int v = tid + i * 256;
            int row = v >> 4, seg = v & 15;
            const __nv_bfloat16* gp = B + (size_t)(kt * GBK + row) * N + bn + seg * 8;
            asm volatile("cp.async.cg.shared.global [%0], [%1], 16;\n" ::
                         "r"(smem_u32(&Bs[s][row][seg * 8])), "l"(gp));
        }
        asm volatile("cp.async.commit_group;\n");
    };

    load_tiles(0, 0);
    int s = 0;
    for (int kt = 0; kt < KT; kt++) {
        asm volatile("cp.async.wait_group 0;\n");
        __syncthreads();
        if (kt + 1 < KT) load_tiles(kt + 1, s ^ 1);
#pragma unroll
        for (int ks = 0; ks < 2; ks++) {
            uint32_t af[4][4];
            uint32_t bf[4][2];
#pragma unroll
            for (int mf = 0; mf < 4; mf++) {
                uint32_t addr = smem_u32(
                    &As[s][wm + mf * 16 + (lane & 15)][ks * 16 + (lane >> 4) * 8]);
                asm volatile(
                    "ldmatrix.sync.aligned.m8n8.x4.shared.b16 {%0,%1,%2,%3}, [%4];\n"
                    : "=r"(af[mf][0]), "=r"(af[mf][1]), "=r"(af[mf][2]), "=r"(af[mf][3])
                    : "r"(addr));
            }
#pragma unroll
            for (int p = 0; p < 2; p++) {
                uint32_t addr = smem_u32(
                    &Bs[s][ks * 16 + (lane & 15)][wn + p * 16 + (lane >> 4) * 8]);
                uint32_t r0, r1, r2, r3;
                asm volatile(
                    "ldmatrix.sync.aligned.m8n8.x4.trans.shared.b16 {%0,%1,%2,%3}, [%4];\n"
                    : "=r"(r0), "=r"(r1), "=r"(r2), "=r"(r3)
                    : "r"(addr));
                bf[p * 2][0] = r0; bf[p * 2][1] = r1;
                bf[p * 2 + 1][0] = r2; bf[p * 2 + 1][1] = r3;
            }
#pragma unroll
            for (int mf = 0; mf < 4; mf++)
#pragma unroll
                for (int nf = 0; nf < 4; nf++) {
                    asm volatile(
                        "mma.sync.aligned.m16n8k16.row.col.f32.bf16.bf16.f32 "
                        "{%0,%1,%2,%3}, {%4,%5,%6,%7}, {%8,%9}, {%0,%1,%2,%3};\n"
                        : "+f"(acc[mf][nf][0]), "+f"(acc[mf][nf][1]),
                          "+f"(acc[mf][nf][2]), "+f"(acc[mf][nf][3])
                        : "r"(af[mf][0]), "r"(af[mf][1]), "r"(af[mf][2]), "r"(af[mf][3]),
                          "r"(bf[nf][0]), "r"(bf[nf][1]));
                }
        }
        s ^= 1;
    }

#pragma unroll
    for (int mf = 0; mf < 4; mf++) {
#pragma unroll
        for (int nf = 0; nf < 4; nf++) {
            int row = bm + wm + mf * 16 + (lane >> 2);
            int col = bn + wn + nf * 8 + (lane & 3) * 2;
            float b0 = 0.f, b1 = 0.f;
            if (HAS_BIAS) { b0 = bias[col]; b1 = bias[col + 1]; }
            float2 v0 = make_float2(acc[mf][nf][0] + b0, acc[mf][nf][1] + b1);
            float2 v1 = make_float2(acc[mf][nf][2] + b0, acc[mf][nf][3] + b1);
            *reinterpret_cast<float2*>(C + (size_t)row * N + col) = v0;
            *reinterpret_cast<float2*>(C + (size_t)(row + 8) * N + col) = v1;
        }
    }
}

// ---------------------------- elementwise after gemm1 -----------------------
// A_bar = exp(-softplus(d)) = 1/(1+e^d);  u = (1-A_bar)*Bm*x_proj;  c = C
__global__ void elemwise_kernel(const float* __restrict__ bx,
                                const float* __restrict__ bbc,
                                const float* __restrict__ bd) {
    int gid = blockIdx.x * 256 + threadIdx.x;       // < kBL*128
    int r   = gid >> 7;
    int n4  = (gid & 127) * 4;
    const float* base = g_proj + (size_t)r * kNP1;
    float4 xp = *(const float4*)(base + n4);
    float4 bm = *(const float4*)(base + 512 + n4);
    float4 cc = *(const float4*)(base + 1024 + n4);
    float4 dd = *(const float4*)(base + 1536 + n4);
    float4 vbx = *(const float4*)(bx + n4);
    float4 vbb = *(const float4*)(bbc + n4);
    float4 vbc = *(const float4*)(bbc + 512 + n4);
    float4 vbd = *(const float4*)(bd + n4);

    float xv[4] = {xp.x + vbx.x, xp.y + vbx.y, xp.z + vbx.z, xp.w + vbx.w};
    float bv[4] = {bm.x + vbb.x, bm.y + vbb.y, bm.z + vbb.z, bm.w + vbb.w};
    float cv[4] = {cc.x + vbc.x, cc.y + vbc.y, cc.z + vbc.z, cc.w + vbc.w};
    float dv[4] = {dd.x + vbd.x, dd.y + vbd.y, dd.z + vbd.z, dd.w + vbd.w};

    float av[4], uv[4];
#pragma unroll
    for (int i = 0; i < 4; i++) {
        float A = 1.0f / (1.0f + expf(dv[i]));      // sigmoid(-d) == exp(-softplus(d))
        av[i] = A;
        uv[i] = (1.0f - A) * bv[i] * xv[i];
    }
    size_t o = (size_t)r * kN + n4;
    *(float4*)(g_a + o) = make_float4(av[0], av[1], av[2], av[3]);
    *(float4*)(g_u + o) = make_float4(uv[0], uv[1], uv[2], uv[3]);
    *(float4*)(g_c + o) = make_float4(cv[0], cv[1], cv[2], cv[3]);
}

// ------------------------------- chunked scan -------------------------------
__global__ void scan_phase1() {                      // per-chunk aggregates
    int n  = threadIdx.x;                            // 0..511
    int ch = blockIdx.x;                             // 0..31
    int b  = blockIdx.y;                             // 0..3
    size_t base = ((size_t)(b * kL + ch * kCH)) * kN + n;
    float Ar = 1.f, Br = 0.f;
#pragma unroll 4
    for (int t = 0; t < kCH; t++) {
        size_t o = base + (size_t)t * kN;
        float a = g_a[o];
        float u = g_u[o];
        Br = fmaf(a, Br, u);
        Ar *= a;
    }
    int idx = (b * kNCH + ch) * kN + n;
    g_Ag[idx] = Ar;
    g_Bg[idx] = Br;
}

__global__ void scan_phase2() {                      // exclusive prefix over chunks
    int n = threadIdx.x;
    int b = blockIdx.x;
    float h = 0.f;
    for (int ch = 0; ch < kNCH; ch++) {
        int idx = (b * kNCH + ch) * kN + n;
        g_H[idx] = h;
        h = fmaf(g_Ag[idx], h, g_Bg[idx]);
    }
}

__global__ void scan_phase3() {                      // final scan, emit packed y1
    int n  = threadIdx.x;
    int ch = blockIdx.x;
    int b  = blockIdx.y;
    int idx = (b * kNCH + ch) * kN + n;
    float h = g_H[idx];
    int row0 = b * kL + ch * kCH;
    size_t base = (size_t)row0 * kN + n;
#pragma unroll 4
    for (int t = 0; t < kCH; t++) {
        size_t o = base + (size_t)t * kN;
        float a = g_a[o], u = g_u[o], c = g_c[o];
        h = fmaf(a, h, u);
        float y = c * h;
        __nv_bfloat16 hi = __float2bfloat16(y);
        __nv_bfloat16 lo = __float2bfloat16(y - __bfloat162float(hi));
        size_t yo = (size_t)(row0 + t) * kKP2 + n;
        g_y1p[yo]        = hi;   // pairs with Wy hi
        g_y1p[yo + 512]  = hi;   // pairs with Wy lo
        g_y1p[yo + 1024] = lo;   // pairs with Wy hi
    }
}

// --------------------------------- launcher ---------------------------------
extern "C" void kernel_launch(void* const* d_in, const int* in_sizes, int n_in,
                              void* d_out, int out_size) {
    const float* x   = (const float*)d_in[0];
    const float* Wx  = (const float*)d_in[1];
    const float* bx  = (const float*)d_in[2];
    const float* Wbc = (const float*)d_in[3];
    const float* bbc = (const float*)d_in[4];
    const float* Wd  = (const float*)d_in[5];
    const float* bd  = (const float*)d_in[6];
    const float* Wy  = (const float*)d_in[7];
    const float* by  = (const float*)d_in[8];
    float* out = (float*)d_out;
    (void)in_sizes; (void)n_in; (void)out_size;

    void *p_xp, *p_wp1, *p_proj, *p_y1p, *p_wyp;
    cudaGetSymbolAddress(&p_xp,   g_xp);
    cudaGetSymbolAddress(&p_wp1,  g_Wp1);
    cudaGetSymbolAddress(&p_proj, g_proj);
    cudaGetSymbolAddress(&p_y1p,  g_y1p);
    cudaGetSymbolAddress(&p_wyp,  g_Wyp);

    pack_x_kernel <<<(kBL * kKP1) / 256, 256>>>(x);
    pack_w1_kernel<<<(kKP1 * kNP1) / 256, 256>>>(Wx, Wbc, Wd);
    pack_wy_kernel<<<(kKP2 * kCout) / 256, 256>>>(Wy);

    gemm_bf16_split<false><<<dim3(kNP1 / GBN, kBL / GBM), 256>>>(
        (const __nv_bfloat16*)p_xp, (const __nv_bfloat16*)p_wp1, nullptr,
        (float*)p_proj, kBL, kNP1, kKP1);

    elemwise_kernel<<<(kBL * 128) / 256, 256>>>(bx, bbc, bd);

    scan_phase1<<<dim3(kNCH, kB), kN>>>();
    scan_phase2<<<kB, kN>>>();
    scan_phase3<<<dim3(kNCH, kB), kN>>>();

    gemm_bf16_split<true><<<dim3(kCout / GBN, kBL / GBM), 256>>>(
        (const __nv_bfloat16*)p_y1p, (const __nv_bfloat16*)p_wyp, by,
        out, kBL, kCout, kKP2);
}

// round 4
// speedup vs baseline: 1.6583x; 1.6583x over previous
#include <cuda_runtime.h>
#include <cuda_bf16.h>
#include <cstdint>

// ---------------------------------------------------------------------------
// S6 block, legacy mma.sync path (tcgen05 unavailable: harness PTX targets
// compute_103 without the 'a' suffix).
// gemm1 (fused elementwise epilogue, permuted W cols) -> chunked scan ->
// gemm2. 3-term bf16 error split with deduplicated hi segments.
// Shapes fixed: B=4, L=4096, Cin=256, N=512, Cout=256.
// ---------------------------------------------------------------------------

constexpr int kBL = 16384, kN = 512, kCout = 256, kL = 4096, kB = 4;
constexpr int kNCH = 32, kCH = 128;

// ------------------------- scratch (device globals) ------------------------
__device__ __nv_bfloat16 g_xp [(size_t)kBL * 512];    // [row][ xh(256) | xl(256) ]
__device__ __nv_bfloat16 g_Wp1[(size_t)512 * 2048];   // [ wh(256)|wl(256) ][ jperm ]
__device__ __nv_bfloat16 g_y1p[(size_t)kBL * 1024];   // [row][ yh(512) | yl(512) ]
__device__ __nv_bfloat16 g_Wyp[(size_t)1024 * 256];   // [ wh(512)|wl(512) ][ j ]
__device__ float g_a[(size_t)kBL * kN];
__device__ float g_u[(size_t)kBL * kN];
__device__ float g_c[(size_t)kBL * kN];
__device__ float g_Ag[kB * kNCH * kN];
__device__ float g_Bg[kB * kNCH * kN];
__device__ float g_H [kB * kNCH * kN];

__device__ __forceinline__ uint32_t smem_u32(const void* p) {
    return (uint32_t)__cvta_generic_to_shared(p);
}

// ------------------------------ pack kernels --------------------------------
__global__ void pack_x_kernel(const float* __restrict__ x) {
    int idx = blockIdx.x * 256 + threadIdx.x;            // kBL*64 total
    int row = idx >> 6, k4 = (idx & 63) << 2;
    float4 v = *(const float4*)(x + (size_t)row * 256 + k4);
    __nv_bfloat16 h0 = __float2bfloat16(v.x), h1 = __float2bfloat16(v.y);
    __nv_bfloat16 h2 = __float2bfloat16(v.z), h3 = __float2bfloat16(v.w);
    __nv_bfloat16 l0 = __float2bfloat16(v.x - __bfloat162float(h0));
    __nv_bfloat16 l1 = __float2bfloat16(v.y - __bfloat162float(h1));
    __nv_bfloat16 l2 = __float2bfloat16(v.z - __bfloat162float(h2));
    __nv_bfloat16 l3 = __float2bfloat16(v.w - __bfloat162float(h3));
    __nv_bfloat162* ph = (__nv_bfloat162*)(g_xp + (size_t)row * 512 + k4);
    ph[0] = __halves2bfloat162(h0, h1);
    ph[1] = __halves2bfloat162(h2, h3);
    __nv_bfloat162* pl = (__nv_bfloat162*)(g_xp + (size_t)row * 512 + 256 + k4);
    pl[0] = __halves2bfloat162(l0, l1);
    pl[1] = __halves2bfloat162(l2, l3);
}

// Permuted W1 columns. For j = n128*128 + w*32 + nf*8 + q2*2 + r:
//   group g = n128*32 + w*8 + (nf>>1)*4 + q2,  member m = (nf&1)*2 + r
//   m: 0=Wx[:,g] 1=Wbc[:,g] 2=Wbc[:,512+g] 3=Wd[:,g]
__global__ void pack_w1_kernel(const float* __restrict__ Wx,
                               const float* __restrict__ Wbc,
                               const float* __restrict__ Wd) {
    int idx = blockIdx.x * 256 + threadIdx.x;            // 512*2048 total
    int kk = idx >> 11, j = idx & 2047;
    int seg = kk >> 8, k = kk & 255;
    int g = (j >> 7) * 32 + ((j >> 5) & 3) * 8 + ((j >> 4) & 1) * 4 + ((j >> 1) & 3);
    int m = ((j >> 3) & 1) * 2 + (j & 1);
    float w;
    if (m == 0)      w = Wx [k * 512  + g];
    else if (m == 1) w = Wbc[k * 1024 + g];
    else if (m == 2) w = Wbc[k * 1024 + 512 + g];
    else             w = Wd [k * 512  + g];
    __nv_bfloat16 hi = __float2bfloat16(w);
    __nv_bfloat16 o  = hi;
    if (seg == 1) o = __float2bfloat16(w - __bfloat162float(hi));
    g_Wp1[(size_t)kk * 2048 + j] = o;
}

__global__ void pack_wy_kernel(const float* __restrict__ Wy) {
    int idx = blockIdx.x * 256 + threadIdx.x;            // 1024*256 total
    int kk = idx >> 8, j = idx & 255;
    int seg = kk >> 9, k = kk & 511;
    float w = Wy[k * 256 + j];
    __nv_bfloat16 hi = __float2bfloat16(w);
    __nv_bfloat16 o  = hi;
    if (seg == 1) o = __float2bfloat16(w - __bfloat162float(hi));
    g_Wyp[(size_t)kk * 256 + j] = o;
}

// ------------------------------ GEMM (mma.sync) -----------------------------
#define STAGES 4
constexpr int A_ST = 128 * 40;                 // elems per A stage (pad 8)
constexpr int B_ST = 32 * 136;                 // elems per B stage (pad 8)
constexpr int SM_B = STAGES * A_ST;
constexpr int GEMM_SMEM = (STAGES * (A_ST + B_ST)) * 2;   // 75776 bytes

// MODE 1: A=g_xp(512), B=g_Wp1(2048), KBASE=256, fused S6 epilogue.
// MODE 2: A=g_y1p(1024), B=g_Wyp(256), KBASE=512, bias epilogue -> out.
template <int MODE>
__global__ void __launch_bounds__(256, 2)
gemm_fused(const __nv_bfloat16* __restrict__ A,
           const __nv_bfloat16* __restrict__ Bw,
           const float* __restrict__ bias,
           const float* __restrict__ bx, const float* __restrict__ bbc,
           const float* __restrict__ bd,
           float* __restrict__ Cout_) {
    extern __shared__ __align__(16) __nv_bfloat16 sm[];
    __nv_bfloat16* As = sm;
    __nv_bfloat16* Bs = sm + SM_B;

    constexpr int KBASE = (MODE == 1) ? 256 : 512;
    constexpr int S  = KBASE / 32;
    constexpr int KT = 3 * S;
    constexpr int strideA = 2 * KBASE;
    constexpr int NB = (MODE == 1) ? 2048 : 256;

    const int tid = threadIdx.x, lane = tid & 31, warp = tid >> 5;
    const int wm = (warp >> 2) * 64, wn = (warp & 3) * 32;
    const int bm = blockIdx.y * 128, bn = blockIdx.x * 128;

    float acc[4][4][4];
#pragma unroll
    for (int i = 0; i < 4; i++)
#pragma unroll
        for (int j = 0; j < 4; j++)
#pragma unroll
            for (int q = 0; q < 4; q++) acc[i][j][q] = 0.f;

    auto load_tile = [&](int kt, int st) {
        int seg = (kt >= 2 * S) ? 2 : ((kt >= S) ? 1 : 0);
        int kk  = kt - seg * S;
        int aoff = ((seg == 2) ? KBASE : 0) + kk * 32;
        int boff = ((seg == 1) ? KBASE : 0) + kk * 32;
        const __nv_bfloat16* Ab = A + (size_t)bm * strideA + aoff;
        __nv_bfloat16* as = As + st * A_ST;
#pragma unroll
        for (int i = 0; i < 2; i++) {
            int c = tid + i * 256;
            int row = c >> 2, sg = c & 3;
            asm volatile("cp.async.cg.shared.global [%0], [%1], 16;" ::
                         "r"(smem_u32(as + row * 40 + sg * 8)),
                         "l"(Ab + (size_t)row * strideA + sg * 8));
        }
        const __nv_bfloat16* Bb = Bw + (size_t)boff * NB + bn;
        __nv_bfloat16* bs = Bs + st * B_ST;
#pragma unroll
        for (int i = 0; i < 2; i++) {
            int c = tid + i * 256;
            int row = c >> 4, sg = c & 15;
            asm volatile("cp.async.cg.shared.global [%0], [%1], 16;" ::
                         "r"(smem_u32(bs + row * 136 + sg * 8)),
                         "l"(Bb + (size_t)row * NB + sg * 8));
        }
        asm volatile("cp.async.commit_group;");
    };

    load_tile(0, 0);
    load_tile(1, 1);
    load_tile(2, 2);

#pragma unroll 1
    for (int kt = 0; kt < KT; kt++) {
        int s = kt & 3;
        if (kt + 2 < KT)      asm volatile("cp.async.wait_group 2;");
        else if (kt + 1 < KT) asm volatile("cp.async.wait_group 1;");
        else                  asm volatile("cp.async.wait_group 0;");
        __syncthreads();
        if (kt + 3 < KT) load_tile(kt + 3, (kt + 3) & 3);

        __nv_bfloat16* as = As + s * A_ST;
        __nv_bfloat16* bs = Bs + s * B_ST;
#pragma unroll
        for (int ks = 0; ks < 2; ks++) {
            uint32_t af[4][4];
            uint32_t bf[4][2];
#pragma unroll
            for (int mf = 0; mf < 4; mf++) {
                uint32_t addr = smem_u32(
                    as + (wm + mf * 16 + (lane & 15)) * 40 + ks * 16 + (lane >> 4) * 8);
                asm volatile(
                    "ldmatrix.sync.aligned.m8n8.x4.shared.b16 {%0,%1,%2,%3}, [%4];\n"
                    : "=r"(af[mf][0]), "=r"(af[mf][1]), "=r"(af[mf][2]), "=r"(af[mf][3])
                    : "r"(addr));
            }
#pragma unroll
            for (int p = 0; p < 2; p++) {
                uint32_t addr = smem_u32(
                    bs + (ks * 16 + (lane & 15)) * 136 + wn + p * 16 + (lane >> 4) * 8);
                uint32_t r0, r1, r2, r3;
                asm volatile(
                    "ldmatrix.sync.aligned.m8n8.x4.trans.shared.b16 {%0,%1,%2,%3}, [%4];\n"
                    : "=r"(r0), "=r"(r1), "=r"(r2), "=r"(r3)
                    : "r"(addr));
                bf[p * 2][0] = r0;     bf[p * 2][1] = r1;
                bf[p * 2 + 1][0] = r2; bf[p * 2 + 1][1] = r3;
            }
#pragma unroll
            for (int mf = 0; mf < 4; mf++) {
#pragma unroll
                for (int nf = 0; nf < 4; nf++) {
                    asm volatile(
                        "mma.sync.aligned.m16n8k16.row.col.f32.bf16.bf16.f32 "
                        "{%0,%1,%2,%3}, {%4,%5,%6,%7}, {%8,%9}, {%0,%1,%2,%3};\n"
                        : "+f"(acc[mf][nf][0]), "+f"(acc[mf][nf][1]),
                          "+f"(acc[mf][nf][2]), "+f"(acc[mf][nf][3])
                        : "r"(af[mf][0]), "r"(af[mf][1]), "r"(af[mf][2]), "r"(af[mf][3]),
                          "r"(bf[nf][0]), "r"(bf[nf][1]));
                }
            }
        }
    }

    if (MODE == 2) {
#pragma unroll
        for (int mf = 0; mf < 4; mf++) {
#pragma unroll
            for (int nf = 0; nf < 4; nf++) {
                int row = bm + wm + mf * 16 + (lane >> 2);
                int col = bn + wn + nf * 8 + (lane & 3) * 2;
                float b0 = bias[col], b1 = bias[col + 1];
                *reinterpret_cast<float2*>(Cout_ + (size_t)row * kCout + col) =
                    make_float2(acc[mf][nf][0] + b0, acc[mf][nf][1] + b1);
                *reinterpret_cast<float2*>(Cout_ + (size_t)(row + 8) * kCout + col) =
                    make_float2(acc[mf][nf][2] + b0, acc[mf][nf][3] + b1);
            }
        }
    } else {
        // Fused S6 elementwise: each thread holds all 4 members of groups
        // gbase (nf 0/1) and gbase+4 (nf 2/3).
        const int gbase = (bn >> 2) + (wn >> 2) + (lane & 3);
        float vbx0 = bx[gbase],        vbx1 = bx[gbase + 4];
        float vbb0 = bbc[gbase],       vbb1 = bbc[gbase + 4];
        float vbc0 = bbc[512 + gbase], vbc1 = bbc[512 + gbase + 4];
        float vbd0 = bd[gbase],        vbd1 = bd[gbase + 4];
#pragma unroll
        for (int mf = 0; mf < 4; mf++) {
            int Rb = bm + wm + mf * 16 + (lane >> 2);
#pragma unroll
            for (int h = 0; h < 2; h++) {
                int R = Rb + h * 8;
                size_t o = (size_t)R * kN;
                {
                    float xv = acc[mf][0][h * 2 + 0] + vbx0;
                    float bv = acc[mf][0][h * 2 + 1] + vbb0;
                    float cc = acc[mf][1][h * 2 + 0] + vbc0;
                    float dd = acc[mf][1][h * 2 + 1] + vbd0;
                    float Aa = 1.0f / (1.0f + expf(dd));
                    g_a[o + gbase] = Aa;
                    g_u[o + gbase] = (1.0f - Aa) * bv * xv;
                    g_c[o + gbase] = cc;
                }
                {
                    float xv = acc[mf][2][h * 2 + 0] + vbx1;
                    float bv = acc[mf][2][h * 2 + 1] + vbb1;
                    float cc = acc[mf][3][h * 2 + 0] + vbc1;
                    float dd = acc[mf][3][h * 2 + 1] + vbd1;
                    float Aa = 1.0f / (1.0f + expf(dd));
                    g_a[o + gbase + 4] = Aa;
                    g_u[o + gbase + 4] = (1.0f - Aa) * bv * xv;
                    g_c[o + gbase + 4] = cc;
                }
            }
        }
    }
}

// ------------------------------- chunked scan -------------------------------
__global__ void scan_phase1() {
    int n = threadIdx.x, ch = blockIdx.x, b = blockIdx.y;
    size_t base = ((size_t)(b * kL + ch * kCH)) * kN + n;
    float Ar = 1.f, Br = 0.f;
#pragma unroll 4
    for (int t = 0; t < kCH; t++) {
        size_t o = base + (size_t)t * kN;
        float a = g_a[o], u = g_u[o];
        Br = fmaf(a, Br, u);
        Ar *= a;
    }
    int idx = (b * kNCH + ch) * kN + n;
    g_Ag[idx] = Ar;
    g_Bg[idx] = Br;
}

__global__ void scan_phase2() {
    int n = threadIdx.x, b = blockIdx.x;
    float h = 0.f;
    for (int ch = 0; ch < kNCH; ch++) {
        int idx = (b * kNCH + ch) * kN + n;
        g_H[idx] = h;
        h = fmaf(g_Ag[idx], h, g_Bg[idx]);
    }
}

__global__ void scan_phase3() {
    int n = threadIdx.x, ch = blockIdx.x, b = blockIdx.y;
    int idx = (b * kNCH + ch) * kN + n;
    float h = g_H[idx];
    int row0 = b * kL + ch * kCH;
    size_t base = (size_t)row0 * kN + n;
#pragma unroll 4
    for (int t = 0; t < kCH; t++) {
        size_t o = base + (size_t)t * kN;
        float a = g_a[o], u = g_u[o], c = g_c[o];
        h = fmaf(a, h, u);
        float y = c * h;
        __nv_bfloat16 hi = __float2bfloat16(y);
        __nv_bfloat16 lo = __float2bfloat16(y - __bfloat162float(hi));
        size_t yo = (size_t)(row0 + t) * 1024 + n;
        g_y1p[yo]       = hi;
        g_y1p[yo + 512] = lo;
    }
}

// --------------------------------- launcher ---------------------------------
extern "C" void kernel_launch(void* const* d_in, const int* in_sizes, int n_in,
                              void* d_out, int out_size) {
    const float* x   = (const float*)d_in[0];
    const float* Wx  = (const float*)d_in[1];
    const float* bx  = (const float*)d_in[2];
    const float* Wbc = (const float*)d_in[3];
    const float* bbc = (const float*)d_in[4];
    const float* Wd  = (const float*)d_in[5];
    const float* bd  = (const float*)d_in[6];
    const float* Wy  = (const float*)d_in[7];
    const float* by  = (const float*)d_in[8];
    float* out = (float*)d_out;
    (void)in_sizes; (void)n_in; (void)out_size;

    void *p_xp, *p_wp1, *p_y1p, *p_wyp;
    cudaGetSymbolAddress(&p_xp,  g_xp);
    cudaGetSymbolAddress(&p_wp1, g_Wp1);
    cudaGetSymbolAddress(&p_y1p, g_y1p);
    cudaGetSymbolAddress(&p_wyp, g_Wyp);

    cudaFuncSetAttribute(gemm_fused<1>, cudaFuncAttributeMaxDynamicSharedMemorySize, GEMM_SMEM);
    cudaFuncSetAttribute(gemm_fused<2>, cudaFuncAttributeMaxDynamicSharedMemorySize, GEMM_SMEM);

    pack_x_kernel <<<(kBL * 64) / 256, 256>>>(x);
    pack_w1_kernel<<<(512 * 2048) / 256, 256>>>(Wx, Wbc, Wd);
    pack_wy_kernel<<<(1024 * 256) / 256, 256>>>(Wy);

    gemm_fused<1><<<dim3(16, 128), 256, GEMM_SMEM>>>(
        (const __nv_bfloat16*)p_xp, (const __nv_bfloat16*)p_wp1,
        nullptr, bx, bbc, bd, nullptr);

    scan_phase1<<<dim3(kNCH, kB), kN>>>();
    scan_phase2<<<kB, kN>>>();
    scan_phase3<<<dim3(kNCH, kB), kN>>>();

    gemm_fused<2><<<dim3(2, 128), 256, GEMM_SMEM>>>(
        (const __nv_bfloat16*)p_y1p, (const __nv_bfloat16*)p_wyp,
        by, nullptr, nullptr, nullptr, out);
}